// round 1
// baseline (speedup 1.0000x reference)
#include <cuda_runtime.h>
#include <cstddef>
#include <cstdint>

// ---------------- problem constants ----------------
#define MAXN   20000
#define NN     32
#define INF    256
#define MID    128
#define OUTF   512
#define NKP    15
#define EXTENT 0.5f
#define INV_EXTENT 2.0f

// ---------------- scratch (allocation-free) ----------------
__device__ float g_x  [(size_t)MAXN * MID];      // conv1 output      10.2 MB
__device__ float g_wf [(size_t)MAXN * NKP*MID];  // wf / wf2          153.6 MB
__device__ float g_dkp[(size_t)MAXN * NKP*3];    // deformed KPs      3.6 MB
__device__ float g_y  [(size_t)MAXN * MID];      // conv2 output      10.2 MB

__device__ __forceinline__ void fma2(float2 &d, float2 a, float2 b) {
    asm("fma.rn.f32x2 %0, %1, %2, %0;"
        : "+l"(reinterpret_cast<unsigned long long&>(d))
        : "l"(reinterpret_cast<unsigned long long&>(a)),
          "l"(reinterpret_cast<unsigned long long&>(b)));
}
__device__ __forceinline__ float lrelu(float x) { return fmaxf(x, 0.1f * x); }

// =====================================================================
// Generic SGEMM:  C = lrelu(A @ B)   (addC=0)
//                 C = lrelu(lrelu(A @ B) + C)  (addC=1)
// A row-major [M,K], B row-major [K,N].  Requires K%16==0, N%128==0.
// BM=BN=128, BK=16, 256 threads, 8x8 per thread, f32x2 accumulation.
// =====================================================================
__global__ __launch_bounds__(256)
void gemm_lrelu_kernel(const float* __restrict__ A, const float* __restrict__ B,
                       float* __restrict__ C, int M, int N, int K, int addC)
{
    constexpr int BM = 128, BN = 128, BK = 16;
    __shared__ float As[BK][BM];
    __shared__ float Bs[BK][BN];

    const int tid  = threadIdx.x;
    const int bm   = blockIdx.y * BM;
    const int bn   = blockIdx.x * BN;
    const int trow = (tid / 16) * 8;
    const int tcol = (tid % 16) * 8;

    float2 acc[8][4];
#pragma unroll
    for (int m = 0; m < 8; m++)
#pragma unroll
        for (int j = 0; j < 4; j++) acc[m][j] = make_float2(0.f, 0.f);

    for (int k0 = 0; k0 < K; k0 += BK) {
        // load A tile 128x16 (transpose into As[k][m]) — 512 float4, 2/thread
#pragma unroll
        for (int i = 0; i < 2; i++) {
            int idx = tid + i * 256;
            int r = idx >> 2;
            int c = (idx & 3) << 2;
            float4 v = make_float4(0.f, 0.f, 0.f, 0.f);
            if (bm + r < M)
                v = *(const float4*)(A + (size_t)(bm + r) * K + k0 + c);
            As[c + 0][r] = v.x; As[c + 1][r] = v.y;
            As[c + 2][r] = v.z; As[c + 3][r] = v.w;
        }
        // load B tile 16x128 — 512 float4, 2/thread
#pragma unroll
        for (int i = 0; i < 2; i++) {
            int idx = tid + i * 256;
            int r = idx >> 5;
            int c = (idx & 31) << 2;
            *(float4*)&Bs[r][c] = *(const float4*)(B + (size_t)(k0 + r) * N + bn + c);
        }
        __syncthreads();

#pragma unroll
        for (int kk = 0; kk < BK; kk++) {
            float a[8];
            float2 b[4];
            {
                float4 t0 = *(const float4*)&As[kk][trow];
                float4 t1 = *(const float4*)&As[kk][trow + 4];
                a[0]=t0.x; a[1]=t0.y; a[2]=t0.z; a[3]=t0.w;
                a[4]=t1.x; a[5]=t1.y; a[6]=t1.z; a[7]=t1.w;
            }
#pragma unroll
            for (int j = 0; j < 4; j++) b[j] = *(const float2*)&Bs[kk][tcol + 2 * j];
#pragma unroll
            for (int m = 0; m < 8; m++) {
                float2 am = make_float2(a[m], a[m]);
#pragma unroll
                for (int j = 0; j < 4; j++) fma2(acc[m][j], am, b[j]);
            }
        }
        __syncthreads();
    }

    // epilogue
#pragma unroll
    for (int m = 0; m < 8; m++) {
        int row = bm + trow + m;
        if (row >= M) continue;
        float v[8];
#pragma unroll
        for (int j = 0; j < 4; j++) { v[2*j] = acc[m][j].x; v[2*j+1] = acc[m][j].y; }
#pragma unroll
        for (int e = 0; e < 8; e++) v[e] = lrelu(v[e]);
        float* cp = C + (size_t)row * N + bn + tcol;
        if (addC) {
            float4 c0 = *(const float4*)cp;
            float4 c1 = *(const float4*)(cp + 4);
            v[0]+=c0.x; v[1]+=c0.y; v[2]+=c0.z; v[3]+=c0.w;
            v[4]+=c1.x; v[5]+=c1.y; v[6]+=c1.z; v[7]+=c1.w;
#pragma unroll
            for (int e = 0; e < 8; e++) v[e] = lrelu(v[e]);
        }
        *(float4*)cp       = make_float4(v[0], v[1], v[2], v[3]);
        *(float4*)(cp + 4) = make_float4(v[4], v[5], v[6], v[7]);
    }
}

// =====================================================================
// Per-point gather + KP-influence + weighted feature aggregation.
// One block per point, 128 threads (one per mid-channel).
// dkp == nullptr -> rigid K_points; else per-point deformed KPs [n,45].
// Writes wf[n, 15*128] with layout k*128 + c (matches w0/K_values flat).
// =====================================================================
__global__ __launch_bounds__(128)
void wf_kernel(const float* __restrict__ points, const int* __restrict__ nbr,
               const float* __restrict__ xf, const float* __restrict__ kp0,
               const float* __restrict__ dkp, float* __restrict__ wf, int n)
{
    const int i = blockIdx.x;
    const int t = threadIdx.x;

    __shared__ int   s_idx[NN];
    __shared__ float s_w[NKP][NN];
    __shared__ float s_ctr[3];

    if (t < 3) s_ctr[t] = points[(size_t)i * 3 + t];
    __syncthreads();

    if (t < NN) {
        int id = nbr[(size_t)i * NN + t];
        s_idx[t] = id;
        float dx = points[(size_t)id * 3 + 0] - s_ctr[0];
        float dy = points[(size_t)id * 3 + 1] - s_ctr[1];
        float dz = points[(size_t)id * 3 + 2] - s_ctr[2];
        const float* kp = dkp ? (dkp + (size_t)i * (NKP * 3)) : kp0;
#pragma unroll
        for (int k = 0; k < NKP; k++) {
            float ex = dx - kp[k * 3 + 0];
            float ey = dy - kp[k * 3 + 1];
            float ez = dz - kp[k * 3 + 2];
            float d = sqrtf(ex * ex + ey * ey + ez * ez);
            s_w[k][t] = fmaxf(1.0f - d * INV_EXTENT, 0.0f);
        }
    }
    __syncthreads();

    float acc[NKP];
#pragma unroll
    for (int k = 0; k < NKP; k++) acc[k] = 0.f;

#pragma unroll 8
    for (int j = 0; j < NN; j++) {
        float f = xf[(size_t)s_idx[j] * MID + t];
#pragma unroll
        for (int k = 0; k < NKP; k++) acc[k] = fmaf(s_w[k][j], f, acc[k]);
    }

    size_t base = (size_t)i * (NKP * MID) + t;
#pragma unroll
    for (int k = 0; k < NKP; k++) wf[base + (size_t)k * MID] = acc[k];
}

// =====================================================================
// f0 GEMM: [n,1920] @ w0[1920,45] + b0, then deformed KPs:
//   dkp[i,o] = K_points[o] + (f0[i,o]) * EXTENT
// BM=128 rows/block, 256 threads, split-K by 2 (h = tid>>7).
// =====================================================================
__global__ __launch_bounds__(256)
void f0_kernel(const float* __restrict__ WF, const float* __restrict__ W0,
               const float* __restrict__ B0, const float* __restrict__ KP,
               float* __restrict__ DKP, int n)
{
    constexpr int KTOT = NKP * MID;   // 1920
    constexpr int NO   = 45;
    __shared__ float As[32][128];
    __shared__ float Bs[32][48];
    __shared__ float Red[128][46];

    const int tid = threadIdx.x;
    const int r   = tid & 127;
    const int h   = tid >> 7;
    const int bm  = blockIdx.x * 128;

    float2 acc[23];
#pragma unroll
    for (int o = 0; o < 23; o++) acc[o] = make_float2(0.f, 0.f);

    for (int k0 = 0; k0 < KTOT; k0 += 32) {
        // A: 128 rows x 32 k — 1024 float4, 4/thread (transposed store)
#pragma unroll
        for (int i = 0; i < 4; i++) {
            int idx = tid + i * 256;
            int rr = idx >> 3;
            int cc = (idx & 7) << 2;
            float4 v = make_float4(0.f, 0.f, 0.f, 0.f);
            if (bm + rr < n)
                v = *(const float4*)(WF + (size_t)(bm + rr) * KTOT + k0 + cc);
            As[cc + 0][rr] = v.x; As[cc + 1][rr] = v.y;
            As[cc + 2][rr] = v.z; As[cc + 3][rr] = v.w;
        }
        // B: 32 x 45 (pad to 48)
#pragma unroll
        for (int i = 0; i < 6; i++) {
            int idx = tid + i * 256;          // 0..1535
            int rr = idx / 48;
            int cc = idx - rr * 48;
            Bs[rr][cc] = (cc < NO) ? W0[(size_t)(k0 + rr) * NO + cc] : 0.f;
        }
        __syncthreads();

#pragma unroll
        for (int kk = 0; kk < 16; kk++) {
            int k = h * 16 + kk;
            float a = As[k][r];
            float2 av = make_float2(a, a);
#pragma unroll
            for (int o2 = 0; o2 < 23; o2++) {
                float2 bv = *(const float2*)&Bs[k][o2 * 2];
                fma2(acc[o2], av, bv);
            }
        }
        __syncthreads();
    }

    if (h == 1) {
#pragma unroll
        for (int o2 = 0; o2 < 23; o2++)
            *(float2*)&Red[r][o2 * 2] = acc[o2];
    }
    __syncthreads();
    if (h == 0 && bm + r < n) {
        size_t base = (size_t)(bm + r) * NO;
#pragma unroll
        for (int o2 = 0; o2 < 23; o2++) {
            float2 v = acc[o2];
            v.x += Red[r][o2 * 2];
            v.y += Red[r][o2 * 2 + 1];
            int o = o2 * 2;
            {
                float f = v.x + B0[o];
                DKP[base + o] = KP[o] + f * EXTENT;
            }
            o = o2 * 2 + 1;
            if (o < NO) {
                float f = v.y + B0[o];
                DKP[base + o] = KP[o] + f * EXTENT;
            }
        }
    }
}

// =====================================================================
extern "C" void kernel_launch(void* const* d_in, const int* in_sizes, int n_in,
                              void* d_out, int out_size)
{
    const float* points   = (const float*)d_in[0];
    const float* features = (const float*)d_in[1];
    const int*   nbr      = (const int*)  d_in[2];
    const float* W1       = (const float*)d_in[3];
    const float* W3       = (const float*)d_in[4];
    const float* Ws       = (const float*)d_in[5];
    const float* Kv       = (const float*)d_in[6];  // [15,128,128] -> [1920,128]
    const float* w0       = (const float*)d_in[7];  // [15,128,45]  -> [1920,45]
    const float* b0       = (const float*)d_in[8];
    const float* KP       = (const float*)d_in[9];  // [15,3]
    float* out = (float*)d_out;

    const int n  = in_sizes[0] / 3;
    const int mb = (n + 127) / 128;

    float *px, *pwf, *pdkp, *py;
    cudaGetSymbolAddress((void**)&px,   g_x);
    cudaGetSymbolAddress((void**)&pwf,  g_wf);
    cudaGetSymbolAddress((void**)&pdkp, g_dkp);
    cudaGetSymbolAddress((void**)&py,   g_y);

    // 1. conv1: x = lrelu(features @ W1)          [n,128]
    gemm_lrelu_kernel<<<dim3(1, mb), 256>>>(features, W1, px, n, MID, INF, 0);
    // 2. rigid influence-weighted features wf     [n,1920]
    wf_kernel<<<n, 128>>>(points, nbr, px, KP, nullptr, pwf, n);
    // 3. f0 = wf @ w0 + b0 -> deformed kernel pts [n,45]
    f0_kernel<<<mb, 256>>>(pwf, w0, b0, KP, pdkp, n);
    // 4. deformed influence-weighted features wf2 [n,1920] (reuse buffer)
    wf_kernel<<<n, 128>>>(points, nbr, px, KP, pdkp, pwf, n);
    // 5. conv2: y = lrelu(wf2 @ Kv)               [n,128]
    gemm_lrelu_kernel<<<dim3(1, mb), 256>>>(pwf, Kv, py, n, MID, NKP * MID, 0);
    // 6. shortcut: out = lrelu(features @ Ws)     [n,512]
    gemm_lrelu_kernel<<<dim3(4, mb), 256>>>(features, Ws, out, n, OUTF, INF, 0);
    // 7. out = lrelu(lrelu(y @ W3) + out)         [n,512]
    gemm_lrelu_kernel<<<dim3(4, mb), 256>>>(py, W3, out, n, OUTF, MID, 1);
}

// round 3
// speedup vs baseline: 2.0033x; 2.0033x over previous
#include <cuda_runtime.h>
#include <cstddef>
#include <cstdint>

// ---------------- problem constants ----------------
#define MAXN   20000
#define NN     32
#define INF    256
#define MID    128
#define OUTF   512
#define NKP    15
#define EXTENT 0.5f
#define INV_EXTENT 2.0f

// ---------------- scratch (allocation-free) ----------------
__device__ float g_x   [(size_t)MAXN * MID];      // conv1 output (tf32-rounded)
__device__ float g_wf  [(size_t)MAXN * NKP*MID];  // wf / wf2     (tf32-rounded)
__device__ float g_dkp [(size_t)MAXN * NKP*3];    // deformed KPs (fp32)
__device__ float g_y   [(size_t)MAXN * MID];      // conv2 output (tf32-rounded)
__device__ float g_feat[(size_t)MAXN * INF];      // features     (tf32-rounded)
// transposed (K-major, tf32-rounded) weights
#define OFF_W1T 0
#define OFF_WST (OFF_W1T + 128*256)
#define OFF_W3T (OFF_WST + 512*256)
#define OFF_KVT (OFF_W3T + 512*128)
#define OFF_W0T (OFF_KVT + 128*1920)
#define WT_TOTAL (OFF_W0T + 64*1920)
__device__ float g_wt[WT_TOTAL];

__device__ __forceinline__ float lrelu(float x) { return fmaxf(x, 0.1f * x); }
__device__ __forceinline__ float rna_tf32(float x) {
    uint32_t r; asm("cvt.rna.tf32.f32 %0, %1;" : "=r"(r) : "f"(x));
    return __uint_as_float(r);
}
__device__ __forceinline__ uint32_t smem_u32(const void* p) {
    uint32_t a;
    asm("{ .reg .u64 t; cvta.to.shared.u64 t, %1; cvt.u32.u64 %0, t; }" : "=r"(a) : "l"(p));
    return a;
}
__device__ __forceinline__ void cpasync16(uint32_t dst, const void* src, bool pred) {
    int sz = pred ? 16 : 0;
    asm volatile("cp.async.cg.shared.global [%0], [%1], 16, %2;"
                 :: "r"(dst), "l"(src), "r"(sz));
}
#define CP_COMMIT() asm volatile("cp.async.commit_group;")
#define CP_WAIT(n)  asm volatile("cp.async.wait_group %0;" :: "n"(n))

__device__ __forceinline__ void mma_tf32(float* d, const uint32_t* a, const uint32_t* b) {
    asm volatile(
        "mma.sync.aligned.m16n8k8.row.col.f32.tf32.tf32.f32 "
        "{%0,%1,%2,%3}, {%4,%5,%6,%7}, {%8,%9}, {%0,%1,%2,%3};"
        : "+f"(d[0]), "+f"(d[1]), "+f"(d[2]), "+f"(d[3])
        : "r"(a[0]), "r"(a[1]), "r"(a[2]), "r"(a[3]), "r"(b[0]), "r"(b[1]));
}

// =====================================================================
// round features to tf32 bit pattern
// =====================================================================
__global__ void round_kernel(const float* __restrict__ in, float* __restrict__ out, int total)
{
    int i = blockIdx.x * 256 + threadIdx.x;
    if (i < total) out[i] = rna_tf32(in[i]);
}

// =====================================================================
// Weight transpose (+pad, +tf32 round): Bt[n*K+k] = (n<N) ? B[k*N+n] : 0
// =====================================================================
__global__ void transpose_pad(const float* __restrict__ B, float* __restrict__ Bt,
                              int K, int N, int Npad)
{
    int idx = blockIdx.x * 256 + threadIdx.x;
    if (idx >= Npad * K) return;
    int nrow = idx / K, k = idx - nrow * K;
    Bt[idx] = (nrow < N) ? rna_tf32(B[(size_t)k * N + nrow]) : 0.0f;
}

// =====================================================================
// TF32 mma.sync GEMM: acc = A[128-tile, :K] @ Bt[BN-tile, :K]^T
// MODE 0: C = lrelu(acc)                       (plain fp32 store)
// MODE 3: C = rna_tf32(lrelu(acc))             (store rounded, feeds next GEMM)
// MODE 1: C = lrelu(lrelu(acc) + C)            (residual add, final)
// MODE 2: dkp[i,o<45] = KP[o] + (acc+b0[o])*EXTENT   (BN=64)
// A row-major [M,K] tf32-rounded, Bt row-major [Npad,K] tf32-rounded, K%32==0.
// =====================================================================
template<int BN, int MODE>
__global__ __launch_bounds__(256)
void mma_gemm(const float* __restrict__ A, const float* __restrict__ Bt,
              float* __restrict__ C, const float* __restrict__ b0,
              const float* __restrict__ KP, int M, int K, int Nf)
{
    constexpr int NW = (BN == 128) ? 4 : 2;   // warps in N
    constexpr int MW = 8 / NW;                // warps in M
    constexpr int WM = 128 / MW;              // 64 or 32
    constexpr int WN = BN / NW;               // 32
    constexpr int AM = WM / 16;               // 4 or 2
    constexpr int AN = WN / 8;                // 4
    constexpr int LDS_PAD = 36;               // floats per row (conflict-free)
    constexpr int ASZF = 128 * LDS_PAD;       // A buffer floats
    constexpr int BSZF = BN * LDS_PAD;

    extern __shared__ __align__(16) float smem[];
    float* As = smem;                // [2][128][36]
    float* Bs = smem + 2 * ASZF;     // [2][BN][36]
    const uint32_t sA = smem_u32(As);
    const uint32_t sB = smem_u32(Bs);

    const int tid  = threadIdx.x;
    const int lane = tid & 31;
    const int g    = lane >> 2;      // group 0..7
    const int tig  = lane & 3;       // thread-in-group
    const int warp = tid >> 5;
    const int wm   = warp / NW;
    const int wn   = warp % NW;
    const int bm   = blockIdx.y * 128;
    const int bn   = blockIdx.x * BN;

    float acc[AM][AN][4];
#pragma unroll
    for (int i = 0; i < AM; i++)
#pragma unroll
        for (int j = 0; j < AN; j++)
#pragma unroll
            for (int e = 0; e < 4; e++) acc[i][j][e] = 0.f;

    const int NT = K >> 5;

    auto load_tile = [&](int it, int buf) {
        const int k0 = it * 32;
#pragma unroll
        for (int i = 0; i < 4; i++) {          // A: 1024 16B chunks
            int idx = tid + i * 256;
            int r = idx >> 3, c4 = (idx & 7) << 2;
            bool p = (bm + r) < M;
            const float* src = A + (size_t)(p ? bm + r : 0) * K + k0 + c4;
            cpasync16(sA + (buf * ASZF + r * LDS_PAD + c4) * 4, src, p);
        }
#pragma unroll
        for (int i = 0; i < BN / 32; i++) {    // B: BN*8 chunks
            int idx = tid + i * 256;
            int r = idx >> 3, c4 = (idx & 7) << 2;
            const float* src = Bt + (size_t)(bn + r) * K + k0 + c4;
            cpasync16(sB + (buf * BSZF + r * LDS_PAD + c4) * 4, src, true);
        }
        CP_COMMIT();
    };

    load_tile(0, 0);
    for (int it = 0; it < NT; it++) {
        const int cur = it & 1;
        if (it + 1 < NT) { load_tile(it + 1, cur ^ 1); CP_WAIT(1); }
        else             { CP_WAIT(0); }
        __syncthreads();

        const float* Ab = As + cur * ASZF;
        const float* Bb = Bs + cur * BSZF;
#pragma unroll
        for (int ks = 0; ks < 4; ks++) {
            const int k = ks * 8 + tig;
            uint32_t af[AM][4], bf[AN][2];
#pragma unroll
            for (int am = 0; am < AM; am++) {
                int r0 = wm * WM + am * 16 + g;
                af[am][0] = __float_as_uint(Ab[r0 * LDS_PAD + k]);
                af[am][1] = __float_as_uint(Ab[(r0 + 8) * LDS_PAD + k]);
                af[am][2] = __float_as_uint(Ab[r0 * LDS_PAD + k + 4]);
                af[am][3] = __float_as_uint(Ab[(r0 + 8) * LDS_PAD + k + 4]);
            }
#pragma unroll
            for (int an = 0; an < AN; an++) {
                int c0 = wn * WN + an * 8 + g;
                bf[an][0] = __float_as_uint(Bb[c0 * LDS_PAD + k]);
                bf[an][1] = __float_as_uint(Bb[c0 * LDS_PAD + k + 4]);
            }
#pragma unroll
            for (int am = 0; am < AM; am++)
#pragma unroll
                for (int an = 0; an < AN; an++)
                    mma_tf32(acc[am][an], af[am], bf[an]);
        }
        __syncthreads();
    }

    // ---------------- epilogue ----------------
#pragma unroll
    for (int am = 0; am < AM; am++) {
        const int r0 = bm + wm * WM + am * 16 + g;
#pragma unroll
        for (int an = 0; an < AN; an++) {
            const int c = bn + wn * WN + an * 8 + tig * 2;
            if (MODE == 2) {
#pragma unroll
                for (int half = 0; half < 2; half++) {
                    int row = r0 + half * 8;
                    if (row >= M) continue;
                    float d0 = acc[am][an][half * 2 + 0];
                    float d1 = acc[am][an][half * 2 + 1];
                    float* dp = C + (size_t)row * (NKP * 3);
                    if (c < NKP * 3)     dp[c]     = KP[c]     + (d0 + b0[c])     * EXTENT;
                    if (c + 1 < NKP * 3) dp[c + 1] = KP[c + 1] + (d1 + b0[c + 1]) * EXTENT;
                }
            } else {
#pragma unroll
                for (int half = 0; half < 2; half++) {
                    int row = r0 + half * 8;
                    if (row >= M) continue;
                    float d0 = lrelu(acc[am][an][half * 2 + 0]);
                    float d1 = lrelu(acc[am][an][half * 2 + 1]);
                    float* cp = C + (size_t)row * Nf + c;
                    if (MODE == 1) {
                        float2 prev = *(const float2*)cp;
                        d0 = lrelu(d0 + prev.x);
                        d1 = lrelu(d1 + prev.y);
                    }
                    if (MODE == 3) { d0 = rna_tf32(d0); d1 = rna_tf32(d1); }
                    *(float2*)cp = make_float2(d0, d1);
                }
            }
        }
    }
}

// =====================================================================
// Per-point gather + KP-influence + weighted feature aggregation (fp32).
// Stores tf32-rounded wf (it is consumed only as an MMA A-operand).
// =====================================================================
__global__ __launch_bounds__(128)
void wf_kernel(const float* __restrict__ points, const int* __restrict__ nbr,
               const float* __restrict__ xf, const float* __restrict__ kp0,
               const float* __restrict__ dkp, float* __restrict__ wf, int n)
{
    const int i = blockIdx.x;
    const int t = threadIdx.x;

    __shared__ int   s_idx[NN];
    __shared__ float s_w[NKP][NN];
    __shared__ float s_ctr[3];

    if (t < 3) s_ctr[t] = points[(size_t)i * 3 + t];
    __syncthreads();

    if (t < NN) {
        int id = nbr[(size_t)i * NN + t];
        s_idx[t] = id;
        float dx = points[(size_t)id * 3 + 0] - s_ctr[0];
        float dy = points[(size_t)id * 3 + 1] - s_ctr[1];
        float dz = points[(size_t)id * 3 + 2] - s_ctr[2];
        const float* kp = dkp ? (dkp + (size_t)i * (NKP * 3)) : kp0;
#pragma unroll
        for (int k = 0; k < NKP; k++) {
            float ex = dx - kp[k * 3 + 0];
            float ey = dy - kp[k * 3 + 1];
            float ez = dz - kp[k * 3 + 2];
            float d = sqrtf(ex * ex + ey * ey + ez * ez);
            s_w[k][t] = fmaxf(1.0f - d * INV_EXTENT, 0.0f);
        }
    }
    __syncthreads();

    float acc[NKP];
#pragma unroll
    for (int k = 0; k < NKP; k++) acc[k] = 0.f;

#pragma unroll 8
    for (int j = 0; j < NN; j++) {
        float f = xf[(size_t)s_idx[j] * MID + t];
#pragma unroll
        for (int k = 0; k < NKP; k++) acc[k] = fmaf(s_w[k][j], f, acc[k]);
    }

    size_t base = (size_t)i * (NKP * MID) + t;
#pragma unroll
    for (int k = 0; k < NKP; k++) wf[base + (size_t)k * MID] = rna_tf32(acc[k]);
}

// =====================================================================
extern "C" void kernel_launch(void* const* d_in, const int* in_sizes, int n_in,
                              void* d_out, int out_size)
{
    const float* points   = (const float*)d_in[0];
    const float* features = (const float*)d_in[1];
    const int*   nbr      = (const int*)  d_in[2];
    const float* W1       = (const float*)d_in[3];
    const float* W3       = (const float*)d_in[4];
    const float* Ws       = (const float*)d_in[5];
    const float* Kv       = (const float*)d_in[6];  // [15,128,128] -> [1920,128]
    const float* w0       = (const float*)d_in[7];  // [15,128,45]  -> [1920,45]
    const float* b0       = (const float*)d_in[8];
    const float* KP       = (const float*)d_in[9];  // [15,3]
    float* out = (float*)d_out;

    const int n  = in_sizes[0] / 3;
    const int mb = (n + 127) / 128;

    float *px, *pwf, *pdkp, *py, *pwt, *pft;
    cudaGetSymbolAddress((void**)&px,   g_x);
    cudaGetSymbolAddress((void**)&pwf,  g_wf);
    cudaGetSymbolAddress((void**)&pdkp, g_dkp);
    cudaGetSymbolAddress((void**)&py,   g_y);
    cudaGetSymbolAddress((void**)&pwt,  g_wt);
    cudaGetSymbolAddress((void**)&pft,  g_feat);

    // dynamic smem: 2*(128+BN)*36*4 bytes
    const int SM128 = 2 * (128 + 128) * 36 * 4;  // 73728
    const int SM64  = 2 * (128 + 64)  * 36 * 4;  // 55296
    cudaFuncSetAttribute(mma_gemm<128,0>, cudaFuncAttributeMaxDynamicSharedMemorySize, SM128);
    cudaFuncSetAttribute(mma_gemm<128,1>, cudaFuncAttributeMaxDynamicSharedMemorySize, SM128);
    cudaFuncSetAttribute(mma_gemm<128,3>, cudaFuncAttributeMaxDynamicSharedMemorySize, SM128);
    cudaFuncSetAttribute(mma_gemm<64,2>,  cudaFuncAttributeMaxDynamicSharedMemorySize, SM64);

    // 0a. round features to tf32 pattern
    round_kernel<<<(n * INF + 255) / 256, 256>>>(features, pft, n * INF);
    // 0b. transpose weights to K-major (+round)
    transpose_pad<<<(128*256 + 255) / 256, 256>>>(W1, pwt + OFF_W1T, 256, 128, 128);
    transpose_pad<<<(512*256 + 255) / 256, 256>>>(Ws, pwt + OFF_WST, 256, 512, 512);
    transpose_pad<<<(512*128 + 255) / 256, 256>>>(W3, pwt + OFF_W3T, 128, 512, 512);
    transpose_pad<<<(128*1920 + 255) / 256, 256>>>(Kv, pwt + OFF_KVT, 1920, 128, 128);
    transpose_pad<<<(64*1920 + 255) / 256, 256>>>(w0, pwt + OFF_W0T, 1920, 45, 64);

    // 1. conv1: x = lrelu(feat @ W1), rounded            [n,128]
    mma_gemm<128,3><<<dim3(1, mb), 256, SM128>>>(pft, pwt + OFF_W1T, px,
                                                 nullptr, nullptr, n, INF, MID);
    // 2. rigid influence-weighted features wf            [n,1920]
    wf_kernel<<<n, 128>>>(points, nbr, px, KP, nullptr, pwf, n);
    // 3. f0 = wf @ w0 + b0 -> deformed kernel points     [n,45]
    mma_gemm<64,2><<<dim3(1, mb), 256, SM64>>>(pwf, pwt + OFF_W0T, pdkp,
                                               b0, KP, n, NKP * MID, 0);
    // 4. deformed influence-weighted features wf2        [n,1920]
    wf_kernel<<<n, 128>>>(points, nbr, px, KP, pdkp, pwf, n);
    // 5. conv2: y = lrelu(wf2 @ Kv), rounded             [n,128]
    mma_gemm<128,3><<<dim3(1, mb), 256, SM128>>>(pwf, pwt + OFF_KVT, py,
                                                 nullptr, nullptr, n, NKP * MID, MID);
    // 6. shortcut: out = lrelu(feat @ Ws)                [n,512]
    mma_gemm<128,0><<<dim3(4, mb), 256, SM128>>>(pft, pwt + OFF_WST, out,
                                                 nullptr, nullptr, n, INF, OUTF);
    // 7. out = lrelu(lrelu(y @ W3) + out)                [n,512]
    mma_gemm<128,1><<<dim3(4, mb), 256, SM128>>>(py, pwt + OFF_W3T, out,
                                                 nullptr, nullptr, n, MID, OUTF);
}

// round 4
// speedup vs baseline: 2.0781x; 1.0373x over previous
#include <cuda_runtime.h>
#include <cstddef>
#include <cstdint>

// ---------------- problem constants ----------------
#define MAXN   20000
#define NN     32
#define INF    256
#define MID    128
#define OUTF   512
#define NKP    15
#define EXTENT 0.5f
#define INV_EXTENT 2.0f

// ---------------- scratch (allocation-free) ----------------
__device__ float g_x   [(size_t)MAXN * MID];      // conv1 output (fp32 exact)
__device__ float g_wf  [(size_t)MAXN * NKP*MID];  // wf / wf2     (tf32-rounded)
__device__ float g_dkp [(size_t)MAXN * NKP*3];    // deformed KPs (fp32)
__device__ float g_y   [(size_t)MAXN * MID];      // conv2 output (tf32-rounded)
__device__ float g_feat[(size_t)MAXN * INF];      // features     (tf32-rounded)
// transposed (K-major, tf32-rounded) weights
#define OFF_WST 0
#define OFF_W3T (OFF_WST + 512*256)
#define OFF_KVT (OFF_W3T + 512*128)
#define OFF_W0T (OFF_KVT + 128*1920)
#define WT_TOTAL (OFF_W0T + 64*1920)
__device__ float g_wt[WT_TOTAL];

__device__ __forceinline__ float lrelu(float x) { return fmaxf(x, 0.1f * x); }
__device__ __forceinline__ float rna_tf32(float x) {
    uint32_t r; asm("cvt.rna.tf32.f32 %0, %1;" : "=r"(r) : "f"(x));
    return __uint_as_float(r);
}
__device__ __forceinline__ void fma2(float2 &d, float2 a, float2 b) {
    asm("fma.rn.f32x2 %0, %1, %2, %0;"
        : "+l"(reinterpret_cast<unsigned long long&>(d))
        : "l"(reinterpret_cast<unsigned long long&>(a)),
          "l"(reinterpret_cast<unsigned long long&>(b)));
}
__device__ __forceinline__ uint32_t smem_u32(const void* p) {
    uint32_t a;
    asm("{ .reg .u64 t; cvta.to.shared.u64 t, %1; cvt.u32.u64 %0, t; }" : "=r"(a) : "l"(p));
    return a;
}
__device__ __forceinline__ void cpasync16(uint32_t dst, const void* src, bool pred) {
    int sz = pred ? 16 : 0;
    asm volatile("cp.async.cg.shared.global [%0], [%1], 16, %2;"
                 :: "r"(dst), "l"(src), "r"(sz));
}
#define CP_COMMIT() asm volatile("cp.async.commit_group;")
#define CP_WAIT(n)  asm volatile("cp.async.wait_group %0;" :: "n"(n))

__device__ __forceinline__ void mma_tf32(float* d, const uint32_t* a, const uint32_t* b) {
    asm volatile(
        "mma.sync.aligned.m16n8k8.row.col.f32.tf32.tf32.f32 "
        "{%0,%1,%2,%3}, {%4,%5,%6,%7}, {%8,%9}, {%0,%1,%2,%3};"
        : "+f"(d[0]), "+f"(d[1]), "+f"(d[2]), "+f"(d[3])
        : "r"(a[0]), "r"(a[1]), "r"(a[2]), "r"(a[3]), "r"(b[0]), "r"(b[1]));
}

// =====================================================================
// round features to tf32 bit pattern (for shortcut GEMM A-operand)
// =====================================================================
__global__ void round_kernel(const float* __restrict__ in, float* __restrict__ out, int total)
{
    int i = blockIdx.x * 256 + threadIdx.x;
    if (i < total) out[i] = rna_tf32(in[i]);
}

// =====================================================================
// Weight transpose (+pad, +tf32 round): Bt[n*K+k] = (n<N) ? B[k*N+n] : 0
// =====================================================================
__global__ void transpose_pad(const float* __restrict__ B, float* __restrict__ Bt,
                              int K, int N, int Npad)
{
    int idx = blockIdx.x * 256 + threadIdx.x;
    if (idx >= Npad * K) return;
    int nrow = idx / K, k = idx - nrow * K;
    Bt[idx] = (nrow < N) ? rna_tf32(B[(size_t)k * N + nrow]) : 0.0f;
}

// =====================================================================
// Exact fp32 SGEMM (f32x2): C = lrelu(A @ B)
// A row-major [M,K], B row-major [K,N]. K%16==0, N%128==0. Used for conv1.
// =====================================================================
__global__ __launch_bounds__(256)
void fp32_gemm(const float* __restrict__ A, const float* __restrict__ B,
               float* __restrict__ C, int M, int N, int K)
{
    constexpr int BM = 128, BN = 128, BK = 16;
    __shared__ float As[BK][BM];
    __shared__ float Bs[BK][BN];

    const int tid  = threadIdx.x;
    const int bm   = blockIdx.y * BM;
    const int bn   = blockIdx.x * BN;
    const int trow = (tid / 16) * 8;
    const int tcol = (tid % 16) * 8;

    float2 acc[8][4];
#pragma unroll
    for (int m = 0; m < 8; m++)
#pragma unroll
        for (int j = 0; j < 4; j++) acc[m][j] = make_float2(0.f, 0.f);

    for (int k0 = 0; k0 < K; k0 += BK) {
#pragma unroll
        for (int i = 0; i < 2; i++) {
            int idx = tid + i * 256;
            int r = idx >> 2;
            int c = (idx & 3) << 2;
            float4 v = make_float4(0.f, 0.f, 0.f, 0.f);
            if (bm + r < M)
                v = *(const float4*)(A + (size_t)(bm + r) * K + k0 + c);
            As[c + 0][r] = v.x; As[c + 1][r] = v.y;
            As[c + 2][r] = v.z; As[c + 3][r] = v.w;
        }
#pragma unroll
        for (int i = 0; i < 2; i++) {
            int idx = tid + i * 256;
            int r = idx >> 5;
            int c = (idx & 31) << 2;
            *(float4*)&Bs[r][c] = *(const float4*)(B + (size_t)(k0 + r) * N + bn + c);
        }
        __syncthreads();

#pragma unroll
        for (int kk = 0; kk < BK; kk++) {
            float a[8];
            float2 b[4];
            {
                float4 t0 = *(const float4*)&As[kk][trow];
                float4 t1 = *(const float4*)&As[kk][trow + 4];
                a[0]=t0.x; a[1]=t0.y; a[2]=t0.z; a[3]=t0.w;
                a[4]=t1.x; a[5]=t1.y; a[6]=t1.z; a[7]=t1.w;
            }
#pragma unroll
            for (int j = 0; j < 4; j++) b[j] = *(const float2*)&Bs[kk][tcol + 2 * j];
#pragma unroll
            for (int m = 0; m < 8; m++) {
                float2 am = make_float2(a[m], a[m]);
#pragma unroll
                for (int j = 0; j < 4; j++) fma2(acc[m][j], am, b[j]);
            }
        }
        __syncthreads();
    }

#pragma unroll
    for (int m = 0; m < 8; m++) {
        int row = bm + trow + m;
        if (row >= M) continue;
        float v[8];
#pragma unroll
        for (int j = 0; j < 4; j++) { v[2*j] = acc[m][j].x; v[2*j+1] = acc[m][j].y; }
#pragma unroll
        for (int e = 0; e < 8; e++) v[e] = lrelu(v[e]);
        float* cp = C + (size_t)row * N + bn + tcol;
        *(float4*)cp       = make_float4(v[0], v[1], v[2], v[3]);
        *(float4*)(cp + 4) = make_float4(v[4], v[5], v[6], v[7]);
    }
}

// =====================================================================
// TF32 mma.sync GEMM: acc = A[128-tile, :K] @ Bt[BN-tile, :K]^T
// MODE 0: C = lrelu(acc)
// MODE 3: C = rna_tf32(lrelu(acc))
// MODE 1: C = lrelu(lrelu(acc) + C)
// MODE 2: dkp[i,o<45] = KP[o] + (acc+b0[o])*EXTENT   (BN=64)
// =====================================================================
template<int BN, int MODE>
__global__ __launch_bounds__(256)
void mma_gemm(const float* __restrict__ A, const float* __restrict__ Bt,
              float* __restrict__ C, const float* __restrict__ b0,
              const float* __restrict__ KP, int M, int K, int Nf)
{
    constexpr int NW = (BN == 128) ? 4 : 2;
    constexpr int MW = 8 / NW;
    constexpr int WM = 128 / MW;
    constexpr int WN = BN / NW;
    constexpr int AM = WM / 16;
    constexpr int AN = WN / 8;
    constexpr int LDS_PAD = 36;
    constexpr int ASZF = 128 * LDS_PAD;
    constexpr int BSZF = BN * LDS_PAD;

    extern __shared__ __align__(16) float smem[];
    float* As = smem;
    float* Bs = smem + 2 * ASZF;
    const uint32_t sA = smem_u32(As);
    const uint32_t sB = smem_u32(Bs);

    const int tid  = threadIdx.x;
    const int lane = tid & 31;
    const int g    = lane >> 2;
    const int tig  = lane & 3;
    const int warp = tid >> 5;
    const int wm   = warp / NW;
    const int wn   = warp % NW;
    const int bm   = blockIdx.y * 128;
    const int bn   = blockIdx.x * BN;

    float acc[AM][AN][4];
#pragma unroll
    for (int i = 0; i < AM; i++)
#pragma unroll
        for (int j = 0; j < AN; j++)
#pragma unroll
            for (int e = 0; e < 4; e++) acc[i][j][e] = 0.f;

    const int NT = K >> 5;

    auto load_tile = [&](int it, int buf) {
        const int k0 = it * 32;
#pragma unroll
        for (int i = 0; i < 4; i++) {
            int idx = tid + i * 256;
            int r = idx >> 3, c4 = (idx & 7) << 2;
            bool p = (bm + r) < M;
            const float* src = A + (size_t)(p ? bm + r : 0) * K + k0 + c4;
            cpasync16(sA + (buf * ASZF + r * LDS_PAD + c4) * 4, src, p);
        }
#pragma unroll
        for (int i = 0; i < BN / 32; i++) {
            int idx = tid + i * 256;
            int r = idx >> 3, c4 = (idx & 7) << 2;
            const float* src = Bt + (size_t)(bn + r) * K + k0 + c4;
            cpasync16(sB + (buf * BSZF + r * LDS_PAD + c4) * 4, src, true);
        }
        CP_COMMIT();
    };

    load_tile(0, 0);
    for (int it = 0; it < NT; it++) {
        const int cur = it & 1;
        if (it + 1 < NT) { load_tile(it + 1, cur ^ 1); CP_WAIT(1); }
        else             { CP_WAIT(0); }
        __syncthreads();

        const float* Ab = As + cur * ASZF;
        const float* Bb = Bs + cur * BSZF;
#pragma unroll
        for (int ks = 0; ks < 4; ks++) {
            const int k = ks * 8 + tig;
            uint32_t af[AM][4], bf[AN][2];
#pragma unroll
            for (int am = 0; am < AM; am++) {
                int r0 = wm * WM + am * 16 + g;
                af[am][0] = __float_as_uint(Ab[r0 * LDS_PAD + k]);
                af[am][1] = __float_as_uint(Ab[(r0 + 8) * LDS_PAD + k]);
                af[am][2] = __float_as_uint(Ab[r0 * LDS_PAD + k + 4]);
                af[am][3] = __float_as_uint(Ab[(r0 + 8) * LDS_PAD + k + 4]);
            }
#pragma unroll
            for (int an = 0; an < AN; an++) {
                int c0 = wn * WN + an * 8 + g;
                bf[an][0] = __float_as_uint(Bb[c0 * LDS_PAD + k]);
                bf[an][1] = __float_as_uint(Bb[c0 * LDS_PAD + k + 4]);
            }
#pragma unroll
            for (int am = 0; am < AM; am++)
#pragma unroll
                for (int an = 0; an < AN; an++)
                    mma_tf32(acc[am][an], af[am], bf[an]);
        }
        __syncthreads();
    }

#pragma unroll
    for (int am = 0; am < AM; am++) {
        const int r0 = bm + wm * WM + am * 16 + g;
#pragma unroll
        for (int an = 0; an < AN; an++) {
            const int c = bn + wn * WN + an * 8 + tig * 2;
            if (MODE == 2) {
#pragma unroll
                for (int half = 0; half < 2; half++) {
                    int row = r0 + half * 8;
                    if (row >= M) continue;
                    float d0 = acc[am][an][half * 2 + 0];
                    float d1 = acc[am][an][half * 2 + 1];
                    float* dp = C + (size_t)row * (NKP * 3);
                    if (c < NKP * 3)     dp[c]     = KP[c]     + (d0 + b0[c])     * EXTENT;
                    if (c + 1 < NKP * 3) dp[c + 1] = KP[c + 1] + (d1 + b0[c + 1]) * EXTENT;
                }
            } else {
#pragma unroll
                for (int half = 0; half < 2; half++) {
                    int row = r0 + half * 8;
                    if (row >= M) continue;
                    float d0 = lrelu(acc[am][an][half * 2 + 0]);
                    float d1 = lrelu(acc[am][an][half * 2 + 1]);
                    float* cp = C + (size_t)row * Nf + c;
                    if (MODE == 1) {
                        float2 prev = *(const float2*)cp;
                        d0 = lrelu(d0 + prev.x);
                        d1 = lrelu(d1 + prev.y);
                    }
                    if (MODE == 3) { d0 = rna_tf32(d0); d1 = rna_tf32(d1); }
                    *(float2*)cp = make_float2(d0, d1);
                }
            }
        }
    }
}

// =====================================================================
// Per-point gather + KP-influence + weighted feature aggregation.
// 4 points per block, 256 threads; thread = (point, channel-pair).
// f32x2 accumulation halves FMA instruction count.
// =====================================================================
__global__ __launch_bounds__(256)
void wf_kernel(const float* __restrict__ points, const int* __restrict__ nbr,
               const float* __restrict__ xf, const float* __restrict__ kp0,
               const float* __restrict__ dkp, float* __restrict__ wf, int n)
{
    const int tid = threadIdx.x;
    const int i0  = blockIdx.x * 4;

    __shared__ int   s_idx[4][NN];
    __shared__ float s_w[4][NKP][NN];
    __shared__ float s_ctr[4][3];

    if (tid < 12) {
        int pt = tid / 3, d = tid - pt * 3;
        int ip = i0 + pt;
        s_ctr[pt][d] = (ip < n) ? points[(size_t)ip * 3 + d] : 0.f;
    }
    __syncthreads();

    if (tid < 128) {
        int pt = tid >> 5, j = tid & 31;
        int ip = i0 + pt;
        if (ip < n) {
            int id = nbr[(size_t)ip * NN + j];
            s_idx[pt][j] = id;
            float dx = points[(size_t)id * 3 + 0] - s_ctr[pt][0];
            float dy = points[(size_t)id * 3 + 1] - s_ctr[pt][1];
            float dz = points[(size_t)id * 3 + 2] - s_ctr[pt][2];
            const float* kp = dkp ? (dkp + (size_t)ip * (NKP * 3)) : kp0;
#pragma unroll
            for (int k = 0; k < NKP; k++) {
                float ex = dx - kp[k * 3 + 0];
                float ey = dy - kp[k * 3 + 1];
                float ez = dz - kp[k * 3 + 2];
                float d = sqrtf(ex * ex + ey * ey + ez * ez);
                s_w[pt][k][j] = fmaxf(1.0f - d * INV_EXTENT, 0.0f);
            }
        }
    }
    __syncthreads();

    const int p  = tid >> 6;          // point within block
    const int t2 = (tid & 63) << 1;   // channel pair start
    const int i  = i0 + p;
    if (i >= n) return;

    float2 acc[NKP];
#pragma unroll
    for (int k = 0; k < NKP; k++) acc[k] = make_float2(0.f, 0.f);

#pragma unroll 8
    for (int j = 0; j < NN; j++) {
        int id = s_idx[p][j];
        float2 f = *(const float2*)(xf + (size_t)id * MID + t2);
#pragma unroll
        for (int k = 0; k < NKP; k++) {
            float w = s_w[p][k][j];
            fma2(acc[k], make_float2(w, w), f);
        }
    }

    size_t base = (size_t)i * (NKP * MID) + t2;
#pragma unroll
    for (int k = 0; k < NKP; k++)
        *(float2*)(wf + base + (size_t)k * MID) =
            make_float2(rna_tf32(acc[k].x), rna_tf32(acc[k].y));
}

// =====================================================================
extern "C" void kernel_launch(void* const* d_in, const int* in_sizes, int n_in,
                              void* d_out, int out_size)
{
    const float* points   = (const float*)d_in[0];
    const float* features = (const float*)d_in[1];
    const int*   nbr      = (const int*)  d_in[2];
    const float* W1       = (const float*)d_in[3];
    const float* W3       = (const float*)d_in[4];
    const float* Ws       = (const float*)d_in[5];
    const float* Kv       = (const float*)d_in[6];
    const float* w0       = (const float*)d_in[7];
    const float* b0       = (const float*)d_in[8];
    const float* KP       = (const float*)d_in[9];
    float* out = (float*)d_out;

    const int n  = in_sizes[0] / 3;
    const int mb = (n + 127) / 128;

    float *px, *pwf, *pdkp, *py, *pwt, *pft;
    cudaGetSymbolAddress((void**)&px,   g_x);
    cudaGetSymbolAddress((void**)&pwf,  g_wf);
    cudaGetSymbolAddress((void**)&pdkp, g_dkp);
    cudaGetSymbolAddress((void**)&py,   g_y);
    cudaGetSymbolAddress((void**)&pwt,  g_wt);
    cudaGetSymbolAddress((void**)&pft,  g_feat);

    const int SM128 = 2 * (128 + 128) * 36 * 4;
    const int SM64  = 2 * (128 + 64)  * 36 * 4;
    cudaFuncSetAttribute(mma_gemm<128,0>, cudaFuncAttributeMaxDynamicSharedMemorySize, SM128);
    cudaFuncSetAttribute(mma_gemm<128,1>, cudaFuncAttributeMaxDynamicSharedMemorySize, SM128);
    cudaFuncSetAttribute(mma_gemm<128,3>, cudaFuncAttributeMaxDynamicSharedMemorySize, SM128);
    cudaFuncSetAttribute(mma_gemm<64,2>,  cudaFuncAttributeMaxDynamicSharedMemorySize, SM64);

    // 0a. round features (tf32) for shortcut
    round_kernel<<<(n * INF + 255) / 256, 256>>>(features, pft, n * INF);
    // 0b. transpose weights to K-major (+round)
    transpose_pad<<<(512*256 + 255) / 256, 256>>>(Ws, pwt + OFF_WST, 256, 512, 512);
    transpose_pad<<<(512*128 + 255) / 256, 256>>>(W3, pwt + OFF_W3T, 128, 512, 512);
    transpose_pad<<<(128*1920 + 255) / 256, 256>>>(Kv, pwt + OFF_KVT, 1920, 128, 128);
    transpose_pad<<<(64*1920 + 255) / 256, 256>>>(w0, pwt + OFF_W0T, 1920, 45, 64);

    // 1. conv1 (EXACT fp32): x = lrelu(features @ W1)   [n,128]
    fp32_gemm<<<dim3(1, mb), 256>>>(features, W1, px, n, MID, INF);
    // 2. rigid influence-weighted features wf           [n,1920]
    wf_kernel<<<(n + 3) / 4, 256>>>(points, nbr, px, KP, nullptr, pwf, n);
    // 3. f0 = wf @ w0 + b0 -> deformed kernel points    [n,45]
    mma_gemm<64,2><<<dim3(1, mb), 256, SM64>>>(pwf, pwt + OFF_W0T, pdkp,
                                               b0, KP, n, NKP * MID, 0);
    // 4. deformed influence-weighted features wf2       [n,1920]
    wf_kernel<<<(n + 3) / 4, 256>>>(points, nbr, px, KP, pdkp, pwf, n);
    // 5. conv2: y = lrelu(wf2 @ Kv), rounded            [n,128]
    mma_gemm<128,3><<<dim3(1, mb), 256, SM128>>>(pwf, pwt + OFF_KVT, py,
                                                 nullptr, nullptr, n, NKP * MID, MID);
    // 6. shortcut: out = lrelu(feat @ Ws)               [n,512]
    mma_gemm<128,0><<<dim3(4, mb), 256, SM128>>>(pft, pwt + OFF_WST, out,
                                                 nullptr, nullptr, n, INF, OUTF);
    // 7. out = lrelu(lrelu(y @ W3) + out)               [n,512]
    mma_gemm<128,1><<<dim3(4, mb), 256, SM128>>>(py, pwt + OFF_W3T, out,
                                                 nullptr, nullptr, n, MID, OUTF);
}